// round 9
// baseline (speedup 1.0000x reference)
#include <cuda_runtime.h>

#define N_ROWS 8000
#define D 9
#define N4 2000            // N_ROWS / 4 (float4 columns)
#define OUT_TPB 256
#define ROWS_PER_BLK 32
#define CHUNK 64           // rows per K1 block
#define NB1 125            // K1 blocks: 125 * 64 = 8000
#define K1_TPB 64

// Scratch (device globals — zero-initialized, no allocation allowed)
__device__ float d_delta[N_ROWS];   // within-chunk inclusive cumsum of (s1-s2)
__device__ float d_csum[NB1];       // per-chunk totals
__device__ float d_spref[NB1];      // exclusive prefix of chunk totals
__device__ float d_g[N_ROWS];
__device__ float d_h[N_ROWS];
__device__ unsigned int d_tick;     // arrival ticket (self-resetting)

// ---------------------------------------------------------------------------
// K1: parallel rowstats + local scans across 125 SMs.
//   delta[r] = sum_d [ ((x-c1)/a1)^2 - ((x-c2)/a2)^2 ]   (log-domain)
//   d_delta  = within-chunk (64-row) inclusive cumsum of delta
//   g[r] = f1[r]-f2[r],  h[r] = f2[r]
// Last-arriving block scans the 125 chunk totals -> d_spref (tiny, L2-hot).
// ---------------------------------------------------------------------------
__global__ void __launch_bounds__(K1_TPB)
k_pro(const float* __restrict__ x,
      const float* __restrict__ a1, const float* __restrict__ c1,
      const float* __restrict__ a2, const float* __restrict__ c2,
      const float* __restrict__ wf1, const float* __restrict__ bf1,
      const float* __restrict__ wf2, const float* __restrict__ bf2)
{
    __shared__ float s_w0tot;
    __shared__ float swt[2];
    __shared__ int   s_last;

    const int t = threadIdx.x;
    const int b = blockIdx.x;
    const unsigned lane = t & 31;
    const int w = t >> 5;

    // ---- rowstats: one row per thread ----
    const int r = b * CHUNK + t;
    const float inv1 = 1.0f / __ldg(a1);
    const float inv2 = 1.0f / __ldg(a2);
    const float k1 = -__ldg(c1) * inv1;
    const float k2 = -__ldg(c2) * inv2;
    float s1 = 0.f, s2 = 0.f;
    float f1 = __ldg(bf1), f2 = __ldg(bf2);
#pragma unroll
    for (int d = 0; d < D; d++) {
        float xv = __ldg(&x[r * D + d]);
        float u1 = fmaf(xv, inv1, k1);
        float u2 = fmaf(xv, inv2, k2);
        s1 = fmaf(u1, u1, s1);
        s2 = fmaf(u2, u2, s2);
        f1 = fmaf(xv, __ldg(&wf1[d]), f1);
        f2 = fmaf(xv, __ldg(&wf2[d]), f2);
    }
    const float delta = s1 - s2;
    d_g[r] = f1 - f2;
    d_h[r] = f2;

    // ---- within-chunk inclusive cumsum (2 warps) ----
    float v = delta;
#pragma unroll
    for (int o = 1; o < 32; o <<= 1) {
        float n = __shfl_up_sync(0xffffffff, v, o);
        if (lane >= o) v += n;
    }
    if (t == 31) s_w0tot = v;
    __syncthreads();
    if (w == 1) v += s_w0tot;
    d_delta[r] = v;
    if (t == CHUNK - 1) d_csum[b] = v;

    __threadfence();                 // publish before arriving
    __syncthreads();
    if (t == 0) {
        unsigned tk = atomicAdd(&d_tick, 1u);
        s_last = (tk == NB1 - 1u);
    }
    __syncthreads();
    if (!s_last) return;

    // ---- last block: tiny two-level scan of 125 chunk totals -> d_spref ----
    __threadfence();                 // acquire
    float c0 = (t < NB1) ? d_csum[t] : 0.0f;
    float c1v = (t + 64 < NB1) ? d_csum[t + 64] : 0.0f;

    float a = c0;                    // scan chunks 0..63
#pragma unroll
    for (int o = 1; o < 32; o <<= 1) {
        float n = __shfl_up_sync(0xffffffff, a, o);
        if (lane >= o) a += n;
    }
    if (lane == 31) swt[w] = a;
    __syncthreads();
    if (w == 1) a += swt[0];
    float total64 = swt[0] + swt[1];
    d_spref[t] = a - c0;             // exclusive prefix for chunk t
    __syncthreads();

    float bsc = c1v;                 // scan chunks 64..124
#pragma unroll
    for (int o = 1; o < 32; o <<= 1) {
        float n = __shfl_up_sync(0xffffffff, bsc, o);
        if (lane >= o) bsc += n;
    }
    if (lane == 31) swt[w] = bsc;
    __syncthreads();
    if (w == 1) bsc += swt[0];
    if (t + 64 < NB1)
        d_spref[t + 64] = total64 + bsc - c1v;

    if (t == 0) d_tick = 0;          // self-reset for graph replays
}

// ---------------------------------------------------------------------------
// K2: out[i,j] = h[i] + g[i]*w1bar[j], with w1bar computed inline once per
// thread: w1bar[j] = 1/(1+exp(spref[j>>6] + d_delta[j])).
// 32 rows per block (amortizes the MUFU recompute + halves metadata traffic).
// g/h staged through SMEM once per block. 256 MB of streaming stores.
// ---------------------------------------------------------------------------
__global__ void __launch_bounds__(OUT_TPB)
k_outer(float* __restrict__ out)
{
    __shared__ float sg[ROWS_PER_BLK];
    __shared__ float shh[ROWS_PER_BLK];

    const int t = threadIdx.x;
    const int i0 = blockIdx.y * ROWS_PER_BLK;

    if (t < ROWS_PER_BLK)            sg[t]  = d_g[i0 + t];
    else if (t < 2 * ROWS_PER_BLK)   shh[t - ROWS_PER_BLK] = d_h[i0 + t - ROWS_PER_BLK];

    const int j4 = blockIdx.x * OUT_TPB + t;
    float4 w4 = make_float4(0.f, 0.f, 0.f, 0.f);
    if (j4 < N4) {
        const float pre = __ldg(&d_spref[(j4 * 4) >> 6]);
        const float4 dl = reinterpret_cast<const float4*>(d_delta)[j4];
        w4.x = 1.0f / (1.0f + __expf(pre + dl.x));
        w4.y = 1.0f / (1.0f + __expf(pre + dl.y));
        w4.z = 1.0f / (1.0f + __expf(pre + dl.z));
        w4.w = 1.0f / (1.0f + __expf(pre + dl.w));
    }
    __syncthreads();

    if (j4 >= N4) return;
    float4* o4 = reinterpret_cast<float4*>(out);

#pragma unroll
    for (int k = 0; k < ROWS_PER_BLK; k++) {
        const int i = i0 + k;
        const float gv = sg[k];
        const float hv = shh[k];
        float4 o;
        o.x = fmaf(gv, w4.x, hv);
        o.y = fmaf(gv, w4.y, hv);
        o.z = fmaf(gv, w4.z, hv);
        o.w = fmaf(gv, w4.w, hv);
        __stcs(&o4[(size_t)i * N4 + j4], o);
    }
}

// ---------------------------------------------------------------------------
extern "C" void kernel_launch(void* const* d_in, const int* in_sizes, int n_in,
                              void* d_out, int out_size)
{
    const float* x   = (const float*)d_in[0];
    const float* a1  = (const float*)d_in[1];
    const float* c1  = (const float*)d_in[2];
    const float* a2  = (const float*)d_in[3];
    const float* c2  = (const float*)d_in[4];
    const float* wf1 = (const float*)d_in[5];
    const float* bf1 = (const float*)d_in[6];
    const float* wf2 = (const float*)d_in[7];
    const float* bf2 = (const float*)d_in[8];
    float* out = (float*)d_out;

    k_pro<<<NB1, K1_TPB>>>(x, a1, c1, a2, c2, wf1, bf1, wf2, bf2);

    dim3 grid((N4 + OUT_TPB - 1) / OUT_TPB, N_ROWS / ROWS_PER_BLK);  // (8, 250)
    k_outer<<<grid, OUT_TPB>>>(out);
}